// round 2
// baseline (speedup 1.0000x reference)
#include <cuda_runtime.h>
#include <math.h>

#define BB 4
#define SS 1024
#define DD 1024
#define HH 16
#define HDIM 64
#define NEGV -10000000000.0f

// Scratch (module-load allocated; no runtime allocs)
__device__ float g_Q[BB*HH*SS*HDIM];
__device__ float g_K[BB*HH*SS*HDIM];
__device__ float g_V[BB*HH*SS*HDIM];
__device__ float g_attn[BB*SS*DD];

// ---------------------------------------------------------------------------
// Projection GEMM: C[(b,s),(h,e)] = X[4096,1024] @ W[h,:, e] + bias[(h,e)]
// Output scattered to g_{Q,K,V}[b,h,s,e].  128x128 tile, BK=8, 8x8 microtile.
// ---------------------------------------------------------------------------
__global__ __launch_bounds__(256, 2)
void proj_kernel(const float* __restrict__ Xq, const float* __restrict__ Xk,
                 const float* __restrict__ Xv,
                 const float* __restrict__ Wq, const float* __restrict__ Wk,
                 const float* __restrict__ Wv,
                 const float* __restrict__ bq, const float* __restrict__ bk,
                 const float* __restrict__ bv)
{
    const float *X, *W, *bias;
    float* out;
    if (blockIdx.z == 0)      { X = Xq; W = Wq; bias = bq; out = g_Q; }
    else if (blockIdx.z == 1) { X = Xk; W = Wk; bias = bk; out = g_K; }
    else                      { X = Xv; W = Wv; bias = bv; out = g_V; }

    __shared__ float As[8][128];
    __shared__ float Bs[8][128];

    const int tid = threadIdx.x;
    const int tx = tid & 15, ty = tid >> 4;
    const int m0 = blockIdx.y * 128, n0 = blockIdx.x * 128;

    const int aRow = tid >> 1, aCol = (tid & 1) * 4;
    const int bRow = tid >> 5, bCol = (tid & 31) * 4;

    float acc[8][8];
    #pragma unroll
    for (int i = 0; i < 8; i++)
        #pragma unroll
        for (int j = 0; j < 8; j++) acc[i][j] = 0.f;

    for (int k0 = 0; k0 < DD; k0 += 8) {
        float4 av = *(const float4*)(X + (size_t)(m0 + aRow) * DD + k0 + aCol);
        const int n = n0 + bCol;
        float4 bv4 = *(const float4*)(W + (size_t)(n >> 6) * (DD * HDIM)
                                        + (size_t)(k0 + bRow) * HDIM + (n & 63));
        As[aCol + 0][aRow] = av.x;
        As[aCol + 1][aRow] = av.y;
        As[aCol + 2][aRow] = av.z;
        As[aCol + 3][aRow] = av.w;
        *(float4*)&Bs[bRow][bCol] = bv4;
        __syncthreads();

        #pragma unroll
        for (int kk = 0; kk < 8; kk++) {
            float ar[8], br[8];
            *(float4*)&ar[0] = *(const float4*)&As[kk][ty * 4];
            *(float4*)&ar[4] = *(const float4*)&As[kk][64 + ty * 4];
            *(float4*)&br[0] = *(const float4*)&Bs[kk][tx * 4];
            *(float4*)&br[4] = *(const float4*)&Bs[kk][64 + tx * 4];
            #pragma unroll
            for (int i = 0; i < 8; i++)
                #pragma unroll
                for (int j = 0; j < 8; j++)
                    acc[i][j] += ar[i] * br[j];
        }
        __syncthreads();
    }

    #pragma unroll
    for (int i = 0; i < 8; i++) {
        const int m  = m0 + ((i < 4) ? (ty * 4 + i) : (64 + ty * 4 + i - 4));
        const int b_ = m >> 10, s_ = m & (SS - 1);
        #pragma unroll
        for (int jh = 0; jh < 2; jh++) {
            const int n  = n0 + ((jh == 0) ? tx * 4 : 64 + tx * 4);
            const int h_ = n >> 6, e_ = n & 63;
            float4 o;
            o.x = acc[i][jh * 4 + 0] + bias[n + 0];
            o.y = acc[i][jh * 4 + 1] + bias[n + 1];
            o.z = acc[i][jh * 4 + 2] + bias[n + 2];
            o.w = acc[i][jh * 4 + 3] + bias[n + 3];
            *(float4*)(out + ((size_t)(b_ * HH + h_) * SS + s_) * HDIM + e_) = o;
        }
    }
}

// ---------------------------------------------------------------------------
// Flash-style attention per (b,h), 64 query rows per block, KV tiles of 32.
// Reproduces reference masking exactly: masked logits get +NEG (counted in
// the softmax denominator), numerators are zeroed (p*m) via s' > -5e9 test.
// ---------------------------------------------------------------------------
__global__ __launch_bounds__(256, 2)
void attn_kernel(const int* __restrict__ mask)
{
    const int bh = blockIdx.y;
    const int b_ = bh >> 4;
    const int h_ = bh & 15;
    const int q0 = blockIdx.x * 64;

    const float* Qp = g_Q + (size_t)bh * SS * HDIM;
    const float* Kp = g_K + (size_t)bh * SS * HDIM;
    const float* Vp = g_V + (size_t)bh * SS * HDIM;

    __shared__ float Qs[64][64];
    __shared__ float Ks[32][68];   // +4 pad: conflict-free row-strided LDS.128
    __shared__ float Vs[32][64];
    __shared__ float Ps[64][33];   // +1 pad: conflict-free column scans
    __shared__ float rowAlpha[64];
    __shared__ float rowInv[64];

    const int tid = threadIdx.x;
    const int tx = tid & 15, ty = tid >> 4;
    const int r0 = ty * 4;         // 4 query rows per thread
    const int e0 = tx * 4;         // 4 output features per thread

    // Load 64x64 Q tile
    #pragma unroll
    for (int i = 0; i < 4; i++) {
        const int idx = tid + i * 256;          // float4 index 0..1023
        const int row = idx >> 4, c4 = (idx & 15) * 4;
        *(float4*)&Qs[row][c4] = *(const float4*)(Qp + (size_t)(q0 + row) * HDIM + c4);
    }

    float O[4][4];
    #pragma unroll
    for (int i = 0; i < 4; i++)
        #pragma unroll
        for (int j = 0; j < 4; j++) O[i][j] = 0.f;

    float rM = -1e30f, rL = 0.f;   // valid for tid < 64 (row = tid)
    const float scale = 0.03125f;  // 1/sqrt(1024)

    for (int t0 = 0; t0 < SS; t0 += 32) {
        // Load K,V tiles (32x64 each)
        #pragma unroll
        for (int i = 0; i < 2; i++) {
            const int idx = tid + i * 256;
            const int row = idx >> 4, c4 = (idx & 15) * 4;
            *(float4*)&Ks[row][c4] = *(const float4*)(Kp + (size_t)(t0 + row) * HDIM + c4);
            *(float4*)&Vs[row][c4] = *(const float4*)(Vp + (size_t)(t0 + row) * HDIM + c4);
        }
        __syncthreads();

        // Scores: rows r0..r0+3, cols {tx, tx+16}
        float sa[4][2];
        #pragma unroll
        for (int i = 0; i < 4; i++) { sa[i][0] = 0.f; sa[i][1] = 0.f; }
        #pragma unroll
        for (int e = 0; e < 64; e += 4) {
            const float4 k0v = *(const float4*)&Ks[tx][e];
            const float4 k1v = *(const float4*)&Ks[tx + 16][e];
            #pragma unroll
            for (int i = 0; i < 4; i++) {
                const float4 qv = *(const float4*)&Qs[r0 + i][e];
                sa[i][0] += qv.x * k0v.x + qv.y * k0v.y + qv.z * k0v.z + qv.w * k0v.w;
                sa[i][1] += qv.x * k1v.x + qv.y * k1v.y + qv.z * k1v.z + qv.w * k1v.w;
            }
        }
        #pragma unroll
        for (int i = 0; i < 4; i++) {
            const int* mrow = mask + (size_t)(b_ * SS + q0 + r0 + i) * SS + t0;
            Ps[r0 + i][tx]      = sa[i][0] * scale + (mrow[tx]      ? 0.f : NEGV);
            Ps[r0 + i][tx + 16] = sa[i][1] * scale + (mrow[tx + 16] ? 0.f : NEGV);
        }
        __syncthreads();

        // Online softmax (thread tid owns row tid)
        if (tid < 64) {
            float m = rM;
            #pragma unroll
            for (int t = 0; t < 32; t++) m = fmaxf(m, Ps[tid][t]);
            const float alpha = __expf(rM - m);
            float lsum = 0.f;
            #pragma unroll
            for (int t = 0; t < 32; t++) {
                const float v = Ps[tid][t];
                const float p = __expf(v - m);
                lsum += p;                           // denominator counts masked terms
                Ps[tid][t] = (v > -5.0e9f) ? p : 0.f; // numerator: p * mask
            }
            rL = rL * alpha + lsum;
            rM = m;
            rowAlpha[tid] = alpha;
        }
        __syncthreads();

        // Rescale accumulators + P@V
        #pragma unroll
        for (int i = 0; i < 4; i++) {
            const float a = rowAlpha[r0 + i];
            #pragma unroll
            for (int j = 0; j < 4; j++) O[i][j] *= a;
        }
        #pragma unroll
        for (int t = 0; t < 32; t++) {
            const float4 vv = *(const float4*)&Vs[t][e0];
            #pragma unroll
            for (int i = 0; i < 4; i++) {
                const float p = Ps[r0 + i][t];
                O[i][0] += p * vv.x;
                O[i][1] += p * vv.y;
                O[i][2] += p * vv.z;
                O[i][3] += p * vv.w;
            }
        }
        __syncthreads();
    }

    if (tid < 64) rowInv[tid] = 1.f / rL;
    __syncthreads();

    #pragma unroll
    for (int i = 0; i < 4; i++) {
        const float inv = rowInv[r0 + i];
        float4 o;
        o.x = O[i][0] * inv; o.y = O[i][1] * inv;
        o.z = O[i][2] * inv; o.w = O[i][3] * inv;
        *(float4*)(g_attn + (size_t)(b_ * SS + q0 + r0 + i) * DD + h_ * HDIM + e0) = o;
    }
}

// ---------------------------------------------------------------------------
// Output projection: out[4096,1024] = g_attn @ Wo + bo
// ---------------------------------------------------------------------------
__global__ __launch_bounds__(256, 2)
void outproj_kernel(const float* __restrict__ Wo, const float* __restrict__ bo,
                    float* __restrict__ out)
{
    __shared__ float As[8][128];
    __shared__ float Bs[8][128];

    const int tid = threadIdx.x;
    const int tx = tid & 15, ty = tid >> 4;
    const int m0 = blockIdx.y * 128, n0 = blockIdx.x * 128;

    const int aRow = tid >> 1, aCol = (tid & 1) * 4;
    const int bRow = tid >> 5, bCol = (tid & 31) * 4;

    float acc[8][8];
    #pragma unroll
    for (int i = 0; i < 8; i++)
        #pragma unroll
        for (int j = 0; j < 8; j++) acc[i][j] = 0.f;

    for (int k0 = 0; k0 < DD; k0 += 8) {
        float4 av = *(const float4*)(g_attn + (size_t)(m0 + aRow) * DD + k0 + aCol);
        float4 bv4 = *(const float4*)(Wo + (size_t)(k0 + bRow) * DD + n0 + bCol);
        As[aCol + 0][aRow] = av.x;
        As[aCol + 1][aRow] = av.y;
        As[aCol + 2][aRow] = av.z;
        As[aCol + 3][aRow] = av.w;
        *(float4*)&Bs[bRow][bCol] = bv4;
        __syncthreads();

        #pragma unroll
        for (int kk = 0; kk < 8; kk++) {
            float ar[8], br[8];
            *(float4*)&ar[0] = *(const float4*)&As[kk][ty * 4];
            *(float4*)&ar[4] = *(const float4*)&As[kk][64 + ty * 4];
            *(float4*)&br[0] = *(const float4*)&Bs[kk][tx * 4];
            *(float4*)&br[4] = *(const float4*)&Bs[kk][64 + tx * 4];
            #pragma unroll
            for (int i = 0; i < 8; i++)
                #pragma unroll
                for (int j = 0; j < 8; j++)
                    acc[i][j] += ar[i] * br[j];
        }
        __syncthreads();
    }

    #pragma unroll
    for (int i = 0; i < 8; i++) {
        const int m = m0 + ((i < 4) ? (ty * 4 + i) : (64 + ty * 4 + i - 4));
        #pragma unroll
        for (int jh = 0; jh < 2; jh++) {
            const int n = n0 + ((jh == 0) ? tx * 4 : 64 + tx * 4);
            float4 o;
            o.x = acc[i][jh * 4 + 0] + bo[n + 0];
            o.y = acc[i][jh * 4 + 1] + bo[n + 1];
            o.z = acc[i][jh * 4 + 2] + bo[n + 2];
            o.w = acc[i][jh * 4 + 3] + bo[n + 3];
            *(float4*)(out + (size_t)m * DD + n) = o;
        }
    }
}

// ---------------------------------------------------------------------------
extern "C" void kernel_launch(void* const* d_in, const int* in_sizes, int n_in,
                              void* d_out, int out_size)
{
    const float* q    = (const float*)d_in[0];
    const float* k    = (const float*)d_in[1];
    const float* v    = (const float*)d_in[2];
    const int*   mask = (const int*)  d_in[3];
    const float* Wq   = (const float*)d_in[4];
    const float* bq   = (const float*)d_in[5];
    const float* Wk   = (const float*)d_in[6];
    const float* bk   = (const float*)d_in[7];
    const float* Wv   = (const float*)d_in[8];
    const float* bv   = (const float*)d_in[9];
    const float* Wo   = (const float*)d_in[10];
    const float* bo   = (const float*)d_in[11];
    float* out = (float*)d_out;

    dim3 g1(8, 32, 3);                 // N/128, M/128, {Q,K,V}
    proj_kernel<<<g1, 256>>>(q, k, v, Wq, Wk, Wv, bq, bk, bv);

    dim3 g2(16, 64);                   // S/64 query tiles, B*H
    attn_kernel<<<g2, 256>>>(mask);

    dim3 g3(8, 32);                    // N/128, M/128
    outproj_kernel<<<g3, 256>>>(Wo, bo, out);
}